// round 2
// baseline (speedup 1.0000x reference)
#include <cuda_runtime.h>

// EffectiveProbability: post = normalize(p * (CM @ c)) per pixel.
// Input row-normalizations cancel against the output normalization, so skipped.
//
// prior/current [B=8, C=21, H=512, W=512] f32, cm [21,21] f32, out [B*H*W, 21] f32.
//
// R2: register-pressure diet. R1 kept cv[21]+pv[21]+post[21] live (74 regs ->
// 3 blocks/SM, 36% occ, DRAM 54%). Now only cv[21] stays in registers; prior
// is consumed in-loop and the unnormalized posterior goes straight to the smem
// staging tile, with per-pixel 1/acc in s_inv. __launch_bounds__(256,6) caps
// regs at 42 -> 48 warps/SM.

#define NCLS 21
#define HWSHIFT 18              // H*W = 512*512 = 2^18
#define HWSZ (1 << HWSHIFT)
#define BLOCK 256

__global__ __launch_bounds__(BLOCK, 6)
void eff_prob_kernel(const float* __restrict__ prior,
                     const float* __restrict__ current,
                     const float* __restrict__ cm,
                     float* __restrict__ out,
                     int npix)
{
    __shared__ float s_cm[NCLS * NCLS];
    __shared__ float s_out[BLOCK * NCLS];
    __shared__ float s_inv[BLOCK];

    const int tid = threadIdx.x;

    for (int i = tid; i < NCLS * NCLS; i += BLOCK) s_cm[i] = cm[i];
    __syncthreads();

    const int n = blockIdx.x * BLOCK + tid;
    if (n < npix) {
        const int  b    = n >> HWSHIFT;
        const int  hw   = n & (HWSZ - 1);
        const long base = (long)b * (NCLS << HWSHIFT) + hw;

        const float* __restrict__ cp = current + base;
        const float* __restrict__ pp = prior + base;

        // Front-batched coalesced loads of the current distribution (high MLP).
        float cv[NCLS];
        #pragma unroll
        for (int j = 0; j < NCLS; j++) cv[j] = cp[(long)j << HWSHIFT];

        float acc = 0.0f;
        #pragma unroll
        for (int i = 0; i < NCLS; i++) {
            float s = 0.0f;
            #pragma unroll
            for (int j = 0; j < NCLS; j++)
                s = fmaf(s_cm[i * NCLS + j], cv[j], s);
            // prior consumed in-loop: no pv[] register array
            const float t = pp[(long)i << HWSHIFT] * s;
            s_out[tid * NCLS + i] = t;       // stride 21: gcd(21,32)=1, conflict-free
            acc += t;
        }
        s_inv[tid] = 1.0f / acc;
    }
    __syncthreads();

    // Flush block tile [BLOCK, 21] linearly: fully coalesced 128B stores.
    const long out_base = (long)blockIdx.x * BLOCK * NCLS;
    const int  valid    = min(BLOCK, npix - blockIdx.x * BLOCK);
    const int  count    = valid * NCLS;
    for (int k = tid; k < count; k += BLOCK)
        out[out_base + k] = s_out[k] * s_inv[k / NCLS];
}

extern "C" void kernel_launch(void* const* d_in, const int* in_sizes, int n_in,
                              void* d_out, int out_size)
{
    const float* prior   = (const float*)d_in[0];
    const float* current = (const float*)d_in[1];
    const float* cm      = (const float*)d_in[2];
    float*       out     = (float*)d_out;

    const int npix = in_sizes[0] / NCLS;   // B*H*W
    const int grid = (npix + BLOCK - 1) / BLOCK;
    eff_prob_kernel<<<grid, BLOCK>>>(prior, current, cm, out, npix);
}